// round 7
// baseline (speedup 1.0000x reference)
#include <cuda_runtime.h>
#include <cuda_bf16.h>
#include <cstdint>

#define NNODES 100000
#define NEDGES 1200000
#define DIM 64

// Scratch: h = x + scatter_sum(relu(x[src]+edge_attr)) lives here between kernels.
__device__ float g_h[(size_t)NNODES * DIM];

// ---------------------------------------------------------------------------
// Kernel 1: h <- x  (vectorized copy)
// ---------------------------------------------------------------------------
__global__ void init_h_kernel(const float4* __restrict__ x4, float4* __restrict__ h4, int n4) {
    int i = blockIdx.x * blockDim.x + threadIdx.x;
    int stride = gridDim.x * blockDim.x;
    for (; i < n4; i += stride) h4[i] = x4[i];
}

// ---------------------------------------------------------------------------
// Kernel 2: per edge, 16 threads; each thread owns one float4 slice.
//   m = relu(x[src] + edge_attr[e]);  h[dst] += m  (vector red, no return)
//   edge_index is int32 (JAX x64 disabled demotes jnp.int64 -> int32).
// ---------------------------------------------------------------------------
__device__ __forceinline__ void red_add_v4(float* addr, float a, float b, float c, float d) {
    asm volatile("red.global.add.v4.f32 [%0], {%1, %2, %3, %4};"
                 :: "l"(addr), "f"(a), "f"(b), "f"(c), "f"(d)
                 : "memory");
}

__global__ void edge_kernel(const float* __restrict__ x,
                            const int* __restrict__ edge_index,
                            const float* __restrict__ edge_attr,
                            float* __restrict__ h) {
    long long g = (long long)blockIdx.x * blockDim.x + threadIdx.x;
    long long e = g >> 4;                 // edge id
    int c = (int)(g & 15) << 2;           // float offset within the 64-wide row
    if (e >= NEDGES) return;

    int src = edge_index[e];
    int dst = edge_index[NEDGES + e];

    const float4 xv = *reinterpret_cast<const float4*>(x + (long long)src * DIM + c);
    const float4 ev = *reinterpret_cast<const float4*>(edge_attr + e * DIM + c);

    float m0 = fmaxf(xv.x + ev.x, 0.0f);
    float m1 = fmaxf(xv.y + ev.y, 0.0f);
    float m2 = fmaxf(xv.z + ev.z, 0.0f);
    float m3 = fmaxf(xv.w + ev.w, 0.0f);

    red_add_v4(h + (long long)dst * DIM + c, m0, m1, m2, m3);
}

// ---------------------------------------------------------------------------
// Kernel 3: fused MLP  out = relu(h @ W1 + b1) @ W2 + b2
//   W1, W2 (each 64x64 f32 = 16KB) + biases staged in shared.
//   One row per thread; row in registers; W read as broadcast LDS.128.
// ---------------------------------------------------------------------------
__global__ __launch_bounds__(256, 1)
void mlp_kernel(const float* __restrict__ h,
                const float* __restrict__ W1, const float* __restrict__ b1,
                const float* __restrict__ W2, const float* __restrict__ b2,
                float* __restrict__ out, int n) {
    __shared__ float4 sW1[DIM * (DIM / 4)];   // sW1[k*16 + c4] = W1[k][4c4..4c4+3]
    __shared__ float4 sW2[DIM * (DIM / 4)];
    __shared__ float  sb1[DIM];
    __shared__ float  sb2[DIM];

    const int tid = threadIdx.x;
    const float4* W1v = reinterpret_cast<const float4*>(W1);
    const float4* W2v = reinterpret_cast<const float4*>(W2);
    for (int i = tid; i < DIM * (DIM / 4); i += blockDim.x) {
        sW1[i] = W1v[i];
        sW2[i] = W2v[i];
    }
    if (tid < DIM) { sb1[tid] = b1[tid]; sb2[tid] = b2[tid]; }
    __syncthreads();

    const int row = blockIdx.x * blockDim.x + tid;
    if (row >= n) return;

    // Load h row into registers (16 x float4)
    float hr[DIM];
    const float4* hrow4 = reinterpret_cast<const float4*>(h + (long long)row * DIM);
    #pragma unroll
    for (int k4 = 0; k4 < DIM / 4; k4++) {
        float4 v = hrow4[k4];
        hr[4 * k4 + 0] = v.x; hr[4 * k4 + 1] = v.y;
        hr[4 * k4 + 2] = v.z; hr[4 * k4 + 3] = v.w;
    }

    // Layer 1: t = relu(hr @ W1 + b1)
    float t[DIM];
    #pragma unroll
    for (int c4 = 0; c4 < DIM / 4; c4++) {
        float a0 = sb1[4 * c4 + 0], a1 = sb1[4 * c4 + 1];
        float a2 = sb1[4 * c4 + 2], a3 = sb1[4 * c4 + 3];
        #pragma unroll
        for (int k = 0; k < DIM; k++) {
            float4 w = sW1[k * (DIM / 4) + c4];   // broadcast across warp
            a0 = fmaf(hr[k], w.x, a0);
            a1 = fmaf(hr[k], w.y, a1);
            a2 = fmaf(hr[k], w.z, a2);
            a3 = fmaf(hr[k], w.w, a3);
        }
        t[4 * c4 + 0] = fmaxf(a0, 0.0f);
        t[4 * c4 + 1] = fmaxf(a1, 0.0f);
        t[4 * c4 + 2] = fmaxf(a2, 0.0f);
        t[4 * c4 + 3] = fmaxf(a3, 0.0f);
    }

    // Layer 2: out = t @ W2 + b2  (streamed stores)
    float4* orow4 = reinterpret_cast<float4*>(out + (long long)row * DIM);
    #pragma unroll
    for (int c4 = 0; c4 < DIM / 4; c4++) {
        float a0 = sb2[4 * c4 + 0], a1 = sb2[4 * c4 + 1];
        float a2 = sb2[4 * c4 + 2], a3 = sb2[4 * c4 + 3];
        #pragma unroll
        for (int k = 0; k < DIM; k++) {
            float4 w = sW2[k * (DIM / 4) + c4];
            a0 = fmaf(t[k], w.x, a0);
            a1 = fmaf(t[k], w.y, a1);
            a2 = fmaf(t[k], w.z, a2);
            a3 = fmaf(t[k], w.w, a3);
        }
        float4 o; o.x = a0; o.y = a1; o.z = a2; o.w = a3;
        orow4[c4] = o;
    }
}

// ---------------------------------------------------------------------------
// Launch
// ---------------------------------------------------------------------------
extern "C" void kernel_launch(void* const* d_in, const int* in_sizes, int n_in,
                              void* d_out, int out_size) {
    const float* x          = (const float*)d_in[0];
    const int*   edge_index = (const int*)d_in[1];   // int32: JAX x64 disabled
    const float* edge_attr  = (const float*)d_in[2];
    const float* W1         = (const float*)d_in[3];
    const float* b1         = (const float*)d_in[4];
    const float* W2         = (const float*)d_in[5];
    const float* b2         = (const float*)d_in[6];
    float*       out        = (float*)d_out;

    float* h;
    cudaGetSymbolAddress((void**)&h, g_h);

    // 1) h <- x
    {
        int n4 = NNODES * DIM / 4;   // 1.6M float4
        init_h_kernel<<<1184, 256>>>((const float4*)x, (float4*)h, n4);
    }

    // 2) scatter relu(x[src]+edge_attr) into h[dst]
    {
        long long total = (long long)NEDGES * 16;
        int threads = 256;
        int blocks = (int)((total + threads - 1) / threads);
        edge_kernel<<<blocks, threads>>>(x, edge_index, edge_attr, h);
    }

    // 3) fused MLP
    {
        int threads = 256;
        int blocks = (NNODES + threads - 1) / threads;
        mlp_kernel<<<blocks, threads>>>(h, W1, b1, W2, b2, out, NNODES);
    }
}